// round 17
// baseline (speedup 1.0000x reference)
#include <cuda_runtime.h>
#include <cuda_fp16.h>
#include <math.h>
#include <stdint.h>

#define BB 64
#define HH 1024
#define INN 1024
#define BH (BB * HH)
#define KSPLIT 8
#define NT 2                    // 2 stages of BK=64 halves per 128-float K slice
#define MB 32                   // batch chunk size

// Scratch (device globals — no allocations allowed).
__device__ float g_part[KSPLIT * 6 * BH];
__device__ float g_lin[6 * BH];
__device__ float g_f[BH];
__device__ float g_o[BH];
__device__ float g_ipv[BH];   // i' * v  (v with bias)
__device__ float g_div[BB];

struct GemmArgs { const float* W[6]; };
struct BiasArgs { const float* b[6]; };

__device__ __forceinline__ uint32_t packh2(float lo, float hi) {
    __half2 h = __floats2half2_rn(lo, hi);
    return *reinterpret_cast<uint32_t*>(&h);
}

__device__ __forceinline__ void mma_f16(float c[4],
                                        uint32_t a0, uint32_t a1, uint32_t a2, uint32_t a3,
                                        uint32_t b0, uint32_t b1) {
    asm("mma.sync.aligned.m16n8k16.row.col.f32.f16.f16.f32 "
        "{%0,%1,%2,%3},{%4,%5,%6,%7},{%8,%9},{%0,%1,%2,%3};"
        : "+f"(c[0]), "+f"(c[1]), "+f"(c[2]), "+f"(c[3])
        : "r"(a0), "r"(a1), "r"(a2), "r"(a3), "r"(b0), "r"(b1));
}

// ---------------------------------------------------------------------------
// Kernel 1: fused GEMMs on fp16 tensor cores for ONE batch chunk of 32.
// Block tile 32(M=batch) x 64(N=h) x 128(Kslice); 8 warps as 2(M) x 4(N),
// warp tile 16x16.  smem 24KB -> 4+ residents.  Same arithmetic as R16.
// ---------------------------------------------------------------------------
__global__ __launch_bounds__(256, 4) void gemm_kernel(const float* __restrict__ x,
                                                      GemmArgs args, int b0) {
    __shared__ uint32_t xs[NT][32 * 32];    // 8 KB
    __shared__ uint32_t ws[NT][64 * 32];    // 16 KB

    const int g    = blockIdx.y;
    const int n0   = blockIdx.x * 64;
    const int z    = blockIdx.z;
    const int kb   = z * 32;                // slice base in float4 units
    const float* __restrict__ W = args.W[g];

    const int tid  = threadIdx.x;
    const int lane = tid & 31;
    const int warp = tid >> 5;
    const int wm   = warp & 1;    // M-warp: rows wm*16
    const int wn   = warp >> 1;   // N-warp: cols wn*16

    const float4* __restrict__ x4 = reinterpret_cast<const float4*>(x);
    const float4* __restrict__ W4 = reinterpret_cast<const float4*>(W);

#pragma unroll
    for (int st = 0; st < NT; ++st) {
        {   // x tile: 32 rows x 8 u4-slots = 256 slots, one per thread
            int r = tid >> 3, c4 = tid & 7;
            float4 f0 = x4[(size_t)(b0 + r) * 256 + kb + st * 16 + c4 * 2];
            float4 f1 = x4[(size_t)(b0 + r) * 256 + kb + st * 16 + c4 * 2 + 1];
            int idx = r * 32 + ((c4 * 4) ^ ((r & 7) << 2));
            *reinterpret_cast<uint4*>(&xs[st][idx]) =
                make_uint4(packh2(f0.x, f0.y), packh2(f0.z, f0.w),
                           packh2(f1.x, f1.y), packh2(f1.z, f1.w));
        }
#pragma unroll
        for (int i = 0; i < 2; ++i) {   // W tile: 64 rows = 512 slots, two per thread
            int s = tid + i * 256;
            int r = s >> 3, c4 = s & 7;
            float4 f0 = W4[(size_t)(n0 + r) * 256 + kb + st * 16 + c4 * 2];
            float4 f1 = W4[(size_t)(n0 + r) * 256 + kb + st * 16 + c4 * 2 + 1];
            int idx = r * 32 + ((c4 * 4) ^ ((r & 7) << 2));
            *reinterpret_cast<uint4*>(&ws[st][idx]) =
                make_uint4(packh2(f0.x, f0.y), packh2(f0.z, f0.w),
                           packh2(f1.x, f1.y), packh2(f1.z, f1.w));
        }
    }
    __syncthreads();

    float acc[2][4];
#pragma unroll
    for (int j = 0; j < 2; ++j)
#pragma unroll
        for (int l = 0; l < 4; ++l) acc[j][l] = 0.f;

    const int q  = lane >> 2;
    const int tt = lane & 3;
    const int sw = q << 2;

    const int arow = (wm * 16 + q) * 32;
    const int brow = (wn * 16 + q) * 32;

#pragma unroll
    for (int t = 0; t < NT; ++t) {
        const uint32_t* __restrict__ X  = xs[t];
        const uint32_t* __restrict__ Wt = ws[t];
#pragma unroll
        for (int kk = 0; kk < 4; ++kk) {
            const int ca  = (kk * 8 + tt) ^ sw;
            const int ca4 = ca ^ 4;

            uint32_t a0 = X[arow + ca];
            uint32_t a1 = X[arow + 8 * 32 + ca];
            uint32_t a2 = X[arow + ca4];
            uint32_t a3 = X[arow + 8 * 32 + ca4];

            uint32_t b00 = Wt[brow + ca],          b01 = Wt[brow + ca4];
            uint32_t b10 = Wt[brow + 8 * 32 + ca], b11 = Wt[brow + 8 * 32 + ca4];

            mma_f16(acc[0], a0, a1, a2, a3, b00, b01);
            mma_f16(acc[1], a0, a1, a2, a3, b10, b11);
        }
    }

    float* __restrict__ Z = g_part + ((size_t)z * 6 + g) * BH;
    const int r0 = b0 + wm * 16 + q;
#pragma unroll
    for (int fn = 0; fn < 2; ++fn) {
        const int c0 = n0 + wn * 16 + fn * 8 + 2 * tt;
        *reinterpret_cast<float2*>(&Z[(size_t)r0 * HH + c0]) =
            make_float2(acc[fn][0], acc[fn][1]);
        *reinterpret_cast<float2*>(&Z[(size_t)(r0 + 8) * HH + c0]) =
            make_float2(acc[fn][2], acc[fn][3]);
    }
}

// ---------------------------------------------------------------------------
// Kernel 2: fold split-K partials + bias + gates + n_t + m_t + divisor.
// One block per batch row; launched per chunk with base b0.
// ---------------------------------------------------------------------------
__global__ __launch_bounds__(256) void gates_kernel(BiasArgs ba,
                                                    const float* __restrict__ n_in,
                                                    const float* __restrict__ m_in,
                                                    float* __restrict__ out, int b0) {
    __shared__ float sbuf[8];
    const int b   = b0 + blockIdx.x;
    const int tid = threadIdx.x;

    float* __restrict__ outN = out + (size_t)BH + (size_t)BB * HH * HH;
    float* __restrict__ outM = outN + BH;

    float4 zz[6];
#pragma unroll
    for (int g = 0; g < 6; ++g) {
        float4 s = reinterpret_cast<const float4*>(ba.b[g])[tid];
#pragma unroll
        for (int z = 0; z < KSPLIT; ++z) {
            float4 p = reinterpret_cast<const float4*>(
                g_part + ((size_t)z * 6 + g) * BH + (size_t)b * HH)[tid];
            s.x += p.x; s.y += p.y; s.z += p.z; s.w += p.w;
        }
        zz[g] = s;
    }

    float4 nin4 = reinterpret_cast<const float4*>(n_in + (size_t)b * HH)[tid];
    float4 min4 = reinterpret_cast<const float4*>(m_in + (size_t)b * HH)[tid];

    const float* it4 = &zz[0].x; const float* ft4 = &zz[1].x;
    const float* ot4 = &zz[2].x; const float* qv4 = &zz[3].x;
    const float* kr4 = &zz[4].x; const float* vv4 = &zz[5].x;
    const float* nI = &nin4.x;   const float* mI = &min4.x;

    float4 fO, oO, ipvO, qO, kO, ntO, mtO;
    float *fO_ = &fO.x, *oO_ = &oO.x, *ipO_ = &ipvO.x, *qO_ = &qO.x,
          *kO_ = &kO.x, *ntO_ = &ntO.x, *mtO_ = &mtO.x;

    float local = 0.f;
#pragma unroll
    for (int c = 0; c < 4; ++c) {
        float it = it4[c], ft = ft4[c], ot = ot4[c], qv = qv4[c];
        float kv = kr4[c] * 0.03125f;   // 1/sqrt(1024)
        float vv = vv4[c];

        float f_sig = 1.f / (1.f + expf(-ft));
        float o_sig = 1.f / (1.f + expf(-ot));
        float ls = (ft >= 0.f) ? -log1pf(expf(-ft)) : (ft - log1pf(expf(ft)));
        float mt = fmaxf(ls + mI[c], it);
        float ip = expf(it - mt);
        float nt = f_sig * nI[c] + ip * kv;

        fO_[c] = f_sig; oO_[c] = o_sig; ipO_[c] = ip * vv;
        qO_[c] = qv;    kO_[c] = kv;    ntO_[c] = nt;   mtO_[c] = mt;
        local += nt * qv;
    }

    reinterpret_cast<float4*>(g_f   + (size_t)b * HH)[tid] = fO;
    reinterpret_cast<float4*>(g_o   + (size_t)b * HH)[tid] = oO;
    reinterpret_cast<float4*>(g_ipv + (size_t)b * HH)[tid] = ipvO;
    reinterpret_cast<float4*>(g_lin + 3 * BH + (size_t)b * HH)[tid] = qO;
    reinterpret_cast<float4*>(g_lin + 4 * BH + (size_t)b * HH)[tid] = kO;
    reinterpret_cast<float4*>(outN + (size_t)b * HH)[tid] = ntO;
    reinterpret_cast<float4*>(outM + (size_t)b * HH)[tid] = mtO;

#pragma unroll
    for (int off = 16; off > 0; off >>= 1)
        local += __shfl_down_sync(0xffffffffu, local, off);
    int lane = tid & 31, w = tid >> 5;
    if (lane == 0) sbuf[w] = local;
    __syncthreads();
    if (w == 0) {
        float v = (lane < 8) ? sbuf[lane] : 0.f;
#pragma unroll
        for (int off = 4; off > 0; off >>= 1)
            v += __shfl_down_sync(0xffffffffu, v, off);
        if (lane == 0) g_div[b] = fmaxf(fabsf(v), 1.f);
    }
}

// ---------------------------------------------------------------------------
// Kernel 3: fused C update + h for one batch chunk.  One warp per row,
// 32 rows per block (1024 threads); grid 1024 per chunk.
// ---------------------------------------------------------------------------
__global__ __launch_bounds__(1024) void update_kernel(const float* __restrict__ C,
                                                      float* __restrict__ out, int b0) {
    __shared__ float4 ks[256], qs[256];
    const int tid  = threadIdx.x;
    const int lane = tid & 31;
    const int row  = b0 * HH / 1 + 0 + blockIdx.x * 32 + (tid >> 5) + b0 * (HH - HH); // see below
    const int r    = b0 * 1024 + blockIdx.x * 32 + (tid >> 5);
    const int b    = r >> 10;
    (void)row;

    if (tid < 256) {
        ks[tid] = reinterpret_cast<const float4*>(g_lin + 4 * BH + b * HH)[tid];
    } else if (tid < 512) {
        qs[tid - 256] = reinterpret_cast<const float4*>(g_lin + 3 * BH + b * HH)[tid - 256];
    }
    __syncthreads();

    const float f   = g_f[r];
    const float ipv = g_ipv[r];

    const float4* __restrict__ Cr = reinterpret_cast<const float4*>(C + (size_t)r * HH);
    float4* __restrict__ Or = reinterpret_cast<float4*>(out + (size_t)BH + (size_t)r * HH);

    float4 c4[8];
#pragma unroll
    for (int j = 0; j < 8; ++j)
        c4[j] = __ldcs(Cr + j * 32 + lane);

    float dot = 0.f;
#pragma unroll
    for (int j = 0; j < 8; ++j) {
        float4 k4 = ks[j * 32 + lane];
        float4 q4 = qs[j * 32 + lane];
        float4 o;
        o.x = fmaf(f, c4[j].x, ipv * k4.x);
        o.y = fmaf(f, c4[j].y, ipv * k4.y);
        o.z = fmaf(f, c4[j].z, ipv * k4.z);
        o.w = fmaf(f, c4[j].w, ipv * k4.w);
        __stcs(Or + j * 32 + lane, o);
        dot = fmaf(o.x, q4.x, dot);
        dot = fmaf(o.y, q4.y, dot);
        dot = fmaf(o.z, q4.z, dot);
        dot = fmaf(o.w, q4.w, dot);
    }

#pragma unroll
    for (int off = 16; off > 0; off >>= 1)
        dot += __shfl_down_sync(0xffffffffu, dot, off);
    if (lane == 0)
        out[r] = g_o[r] * dot / g_div[b];
}

// ---------------------------------------------------------------------------
// Launch: two batch chunks; chunk-B gemm+gates on a forked stream hide under
// chunk-A's HBM-bound update.  Streams/events are created once on the first
// (non-captured correctness) call; during capture the fork/join event pattern
// builds a multi-stream graph.  Work submitted is identical on every call.
// ---------------------------------------------------------------------------
extern "C" void kernel_launch(void* const* d_in, const int* in_sizes, int n_in,
                              void* d_out, int out_size) {
    const float* x = (const float*)d_in[0];
    const float* C = (const float*)d_in[1];
    const float* n = (const float*)d_in[2];
    const float* m = (const float*)d_in[3];

    GemmArgs ga;
    BiasArgs ba;
    for (int g = 0; g < 6; ++g) {
        ga.W[g] = (const float*)d_in[4 + 2 * g];
        ba.b[g] = (const float*)d_in[5 + 2 * g];
    }

    float* out = (float*)d_out;

    static cudaStream_t s2 = 0;
    static cudaEvent_t evF = 0, evJ = 0;
    static int inited = 0, ok = 0;
    if (!inited) {
        inited = 1;
        ok = (cudaStreamCreateWithFlags(&s2, cudaStreamNonBlocking) == cudaSuccess) &&
             (cudaEventCreateWithFlags(&evF, cudaEventDisableTiming) == cudaSuccess) &&
             (cudaEventCreateWithFlags(&evJ, cudaEventDisableTiming) == cudaSuccess);
    }

    const dim3 gg(HH / 64, 6, KSPLIT);

    if (ok) {
        gemm_kernel<<<gg, 256>>>(x, ga, 0);                 // chunk A
        cudaEventRecord(evF, 0);
        cudaStreamWaitEvent(s2, evF, 0);
        gemm_kernel<<<gg, 256, 0, s2>>>(x, ga, MB);         // chunk B (forked)
        gates_kernel<<<MB, 256, 0, s2>>>(ba, n, m, out, MB);
        gates_kernel<<<MB, 256>>>(ba, n, m, out, 0);
        update_kernel<<<MB * HH / 32, 1024>>>(C, out, 0);   // hides chunk-B gemm/gates
        cudaEventRecord(evJ, s2);
        cudaStreamWaitEvent(0, evJ, 0);
        update_kernel<<<MB * HH / 32, 1024>>>(C, out, MB);
    } else {
        gemm_kernel<<<gg, 256>>>(x, ga, 0);
        gemm_kernel<<<gg, 256>>>(x, ga, MB);
        gates_kernel<<<MB, 256>>>(ba, n, m, out, 0);
        gates_kernel<<<MB, 256>>>(ba, n, m, out, MB);
        update_kernel<<<MB * HH / 32, 1024>>>(C, out, 0);
        update_kernel<<<MB * HH / 32, 1024>>>(C, out, MB);
    }
}